// round 6
// baseline (speedup 1.0000x reference)
#include <cuda_runtime.h>

#define SLOPE 0.01f
#define EPSBN 1e-5f
#define TILE  64
#define PAD   64
#define TPAD  132     // row stride (floats) of transposed xr tile; %4==0 for LDS.128
#define NPOS  65536

// ---------------- device scratch (no allocations allowed) ----------------
__device__ float g_w1t[16384];   // [k][o] transposed, BN-folded
__device__ float g_w2t[16384];
__device__ float g_w3t[16384];   // logits rows only (o<128)
__device__ float g_wrt[16384];   // reg1, BN-folded
__device__ float g_b1[128];
__device__ float g_b2[128];
__device__ float g_b3[128];
__device__ float g_br[128];
__device__ float g_wm[128];      // mask row of cl3_w (o==128)
__device__ float g_bm;
__device__ float4 g_moe4[131072]; // [expert][c/4][lane] float4 repack of cm2_w (2MB)

__device__ __forceinline__ float lrelu(float v) { return v >= 0.0f ? v : SLOPE * v; }

// packed f32x2 helpers (FFMA2 path — ptxas never emits this, PTX only)
__device__ __forceinline__ unsigned long long pk2(float x) {
    unsigned long long r;
    asm("mov.b64 %0, {%1, %1};" : "=l"(r) : "f"(x));
    return r;
}
__device__ __forceinline__ void fma2(unsigned long long& d,
                                     unsigned long long a, unsigned long long b) {
    asm("fma.rn.f32x2 %0, %1, %2, %0;" : "+l"(d) : "l"(a), "l"(b));
}
__device__ __forceinline__ float2 up2(unsigned long long v) {
    float2 r;
    asm("mov.b64 {%0, %1}, %2;" : "=f"(r.x), "=f"(r.y) : "l"(v));
    return r;
}

// ---------------- merged prep: fold BN, transpose weights, repack MoE ----------------
__global__ void prep_all_kernel(const float* __restrict__ cl1_w, const float* __restrict__ cl1_b,
                                const float* __restrict__ g1,    const float* __restrict__ be1,
                                const float* __restrict__ m1,    const float* __restrict__ v1,
                                const float* __restrict__ cl2_w, const float* __restrict__ cl2_b,
                                const float* __restrict__ cl3_w, const float* __restrict__ cl3_b,
                                const float* __restrict__ reg1_w,const float* __restrict__ reg1_b,
                                const float* __restrict__ gr,    const float* __restrict__ ber,
                                const float* __restrict__ mr,    const float* __restrict__ vr,
                                const float* __restrict__ cm2_w)
{
    int tid = blockIdx.x * blockDim.x + threadIdx.x;   // 0..131071

    // MoE repack: [e][cg][lane] <- cm2_w[e][cg*4 + 0..3][lane]
    {
        int e  = tid >> 10;
        int cg = (tid >> 5) & 31;
        int j  = tid & 31;
        const float* src = cm2_w + e * 4096 + (cg * 4) * 32 + j;
        g_moe4[tid] = make_float4(src[0], src[32], src[64], src[96]);
    }

    if (tid < 16384) {
        int o = tid >> 7, k = tid & 127;
        float s1 = g1[o] * rsqrtf(v1[o] + EPSBN);
        float sr = gr[o] * rsqrtf(vr[o] + EPSBN);
        g_w1t[k * 128 + o] = cl1_w[o * 128 + k] * s1;
        g_wrt[k * 128 + o] = reg1_w[o * 128 + k] * sr;
        g_w2t[k * 128 + o] = cl2_w[o * 128 + k];
        g_w3t[k * 128 + o] = cl3_w[o * 128 + k];
    }
    if (tid < 128) {
        float s = g1[tid] * rsqrtf(v1[tid] + EPSBN);
        g_b1[tid] = cl1_b[tid] * s + be1[tid] - m1[tid] * s;
        float s2 = gr[tid] * rsqrtf(vr[tid] + EPSBN);
        g_br[tid] = reg1_b[tid] * s2 + ber[tid] - mr[tid] * s2;
        g_b2[tid] = cl2_b[tid];
        g_b3[tid] = cl3_b[tid];
        g_wm[tid] = cl3_w[128 * 128 + tid];
        if (tid == 0) g_bm = cl3_b[128];
    }
}

// ---------------- 128x128 x 64 GEMM tile via FFMA2 ----------------
// sIn: [128][PAD] input tile. wT: [k][o] transposed weights (L2-hot global).
// sW: single 16x128 staging buffer, register-prefetched double buffering.
// Result unpacked into f[8][4]: channels ty*8..+7, positions tx*4..+3.
__device__ __forceinline__ void gemm_tile(const float* __restrict__ wT,
                                          const float* sIn, float* sW,
                                          float f[8][4])
{
    const int t  = threadIdx.x;
    const int ty = t >> 4, tx = t & 15;
    const float4* wg  = (const float4*)wT;
    float4*       ws4 = (float4*)sW;

    unsigned long long acc[4][4];
#pragma unroll
    for (int i = 0; i < 4; i++)
#pragma unroll
        for (int j = 0; j < 4; j++) acc[i][j] = 0ull;

    // prefetch chunk 0 (16 k-rows x 128 o = 512 float4)
    float4 p0 = wg[t];
    float4 p1 = wg[t + 256];

#pragma unroll 1
    for (int kk = 0; kk < 8; kk++) {
        ws4[t]       = p0;
        ws4[t + 256] = p1;
        __syncthreads();
        if (kk < 7) {
            p0 = wg[(kk + 1) * 512 + t];
            p1 = wg[(kk + 1) * 512 + 256 + t];
        }
        const float* inb = sIn + kk * 16 * PAD;
#pragma unroll
        for (int k = 0; k < 16; k++) {
            // channel pairs come packed straight out of LDS.128
            ulonglong2 a01 = *(const ulonglong2*)(sW + k * 128 + ty * 8);
            ulonglong2 a23 = *(const ulonglong2*)(sW + k * 128 + ty * 8 + 4);
            float4 b4 = *(const float4*)(inb + k * PAD + tx * 4);
            unsigned long long b0 = pk2(b4.x), b1 = pk2(b4.y),
                               b2 = pk2(b4.z), b3 = pk2(b4.w);
            fma2(acc[0][0], a01.x, b0); fma2(acc[0][1], a01.x, b1);
            fma2(acc[0][2], a01.x, b2); fma2(acc[0][3], a01.x, b3);
            fma2(acc[1][0], a01.y, b0); fma2(acc[1][1], a01.y, b1);
            fma2(acc[1][2], a01.y, b2); fma2(acc[1][3], a01.y, b3);
            fma2(acc[2][0], a23.x, b0); fma2(acc[2][1], a23.x, b1);
            fma2(acc[2][2], a23.x, b2); fma2(acc[2][3], a23.x, b3);
            fma2(acc[3][0], a23.y, b0); fma2(acc[3][1], a23.y, b1);
            fma2(acc[3][2], a23.y, b2); fma2(acc[3][3], a23.y, b3);
        }
        __syncthreads();
    }

#pragma unroll
    for (int ip = 0; ip < 4; ip++)
#pragma unroll
        for (int j = 0; j < 4; j++) {
            float2 u = up2(acc[ip][j]);
            f[2 * ip][j]     = u.x;
            f[2 * ip + 1][j] = u.y;
        }
}

// ---------------- fused main kernel ----------------
// smem layout (floats):
//   region0: [0, 64*TPAD)      x tile [ch][PAD] initially; xr tile [pos][TPAD] after R1
//   sB:      [64*TPAD, +128*PAD)
//   sW:      staging 2048 floats (aliased by argmax scratch afterwards)
//   sInd:    64 ints
__global__ void __launch_bounds__(256, 3)
fused_kernel(const float* __restrict__ x_in,
             const float* __restrict__ cm2_b,
             const float* __restrict__ cm3_w, const float* __restrict__ cm3_b,
             float* __restrict__ out)
{
    extern __shared__ float sm[];
    float* sA   = sm;                      // x tile as [128][PAD] (32768 < 64*TPAD)
    float* sAT  = sm;                      // xr tile as [64][TPAD] (same region)
    float* sB   = sm + 64 * TPAD;          // 128 * PAD
    float* sW   = sB + 128 * PAD;          // 16 * 128 staging
    float* sRv  = sW;                      // alias: argmax vals
    int*   sRi  = (int*)(sW + 1024);       // alias: argmax idx
    int*   sInd = (int*)(sW + 2048);       // 64

    const int t  = threadIdx.x;
    const int ty = t >> 4, tx = t & 15;
    const int bb = blockIdx.x >> 7;            // batch (8192/64 = 128 tiles per batch)
    const int w0 = (blockIdx.x & 127) * TILE;  // position offset within batch
    const float* xb = x_in + (size_t)bb * 128 * 8192 + w0;

    // stage x_in tile: [c][pos]
#pragma unroll
    for (int j = 0; j < 8; j++) {
        int idx = t + j * 256;
        int c = idx >> 4, p4 = idx & 15;
        float4 v = *(const float4*)(xb + c * 8192 + p4 * 4);
        *(float4*)(sA + c * PAD + p4 * 4) = v;
    }
    __syncthreads();

    float f[8][4];

    // ---- L1: y1 = lrelu(bn(cl1 @ x)) : sA -> sB ----
    gemm_tile(g_w1t, sA, sW, f);
#pragma unroll
    for (int i = 0; i < 8; i++) {
        float bi = g_b1[ty * 8 + i];
#pragma unroll
        for (int j = 0; j < 4; j++) f[i][j] = lrelu(f[i][j] + bi);
        *(float4*)(sB + (ty * 8 + i) * PAD + tx * 4) =
            make_float4(f[i][0], f[i][1], f[i][2], f[i][3]);
    }

    // ---- R1: xr = lrelu(bn(reg1 @ x)) : sA -> TRANSPOSED sAT[pos][ch] ----
    gemm_tile(g_wrt, sA, sW, f);   // final sync inside: all reads of sA done
#pragma unroll
    for (int i = 0; i < 8; i++) {
        float bi = g_br[ty * 8 + i];
#pragma unroll
        for (int j = 0; j < 4; j++) f[i][j] = lrelu(f[i][j] + bi);
    }
#pragma unroll
    for (int j = 0; j < 4; j++)
#pragma unroll
        for (int ip = 0; ip < 4; ip++)
            *(float2*)(sAT + (tx * 4 + j) * TPAD + ty * 8 + 2 * ip) =
                make_float2(f[2 * ip][j], f[2 * ip + 1][j]);

    // ---- L2: y2 = lrelu(cl2 @ y1) : sB -> sB ----
    gemm_tile(g_w2t, sB, sW, f);   // first sync inside orders the sAT/sB writes above
#pragma unroll
    for (int i = 0; i < 8; i++) {
        float bi = g_b2[ty * 8 + i];
#pragma unroll
        for (int j = 0; j < 4; j++) f[i][j] = lrelu(f[i][j] + bi);
        *(float4*)(sB + (ty * 8 + i) * PAD + tx * 4) =
            make_float4(f[i][0], f[i][1], f[i][2], f[i][3]);
    }

    // ---- L3: logits = cl3 @ y2 (128 channels) : sB -> regs ----
    gemm_tile(g_w3t, sB, sW, f);   // after final sync, sW is dead -> alias OK
#pragma unroll
    for (int i = 0; i < 8; i++) {
        float bi = g_b3[ty * 8 + i];
#pragma unroll
        for (int j = 0; j < 4; j++) f[i][j] += bi;
    }

    // local argmax over this thread's 8 channels (first-occurrence on ties)
#pragma unroll
    for (int j = 0; j < 4; j++) {
        float bv = f[0][j];
        int bi = 0;
#pragma unroll
        for (int i = 1; i < 8; i++)
            if (f[i][j] > bv) { bv = f[i][j]; bi = i; }
        sRv[ty * 64 + tx * 4 + j] = bv;
        sRi[ty * 64 + tx * 4 + j] = ty * 8 + bi;
    }
    __syncthreads();

    if (t < 64) {
        // reduce argmax across 16 channel groups (ascending -> first occurrence kept)
        float bv = sRv[t];
        int bi = sRi[t];
#pragma unroll
        for (int r = 1; r < 16; r++) {
            float v = sRv[r * 64 + t];
            if (v > bv) { bv = v; bi = sRi[r * 64 + t]; }
        }
        sInd[t] = bi;
    } else if (t < 128) {
        // mask channel: dot(y2[:,p], wm) + bm via 4 partial chains, lrelu
        int p = t - 64;
        float m0 = g_bm, m1 = 0.0f, m2 = 0.0f, m3 = 0.0f;
#pragma unroll 8
        for (int k = 0; k < 128; k += 4) {
            m0 = fmaf(sB[(k + 0) * PAD + p], g_wm[k + 0], m0);
            m1 = fmaf(sB[(k + 1) * PAD + p], g_wm[k + 1], m1);
            m2 = fmaf(sB[(k + 2) * PAD + p], g_wm[k + 2], m2);
            m3 = fmaf(sB[(k + 3) * PAD + p], g_wm[k + 3], m3);
        }
        out[NPOS + bb * 8192 + w0 + p] = lrelu((m0 + m1) + (m2 + m3));
    }
    __syncthreads();

    // ---- MoE regression: warp per position, lane = hidden unit ----
    // xr is [pos][ch] contiguous -> 8 broadcast LDS.128 per 32-ch block.
    // 4 partial accumulators break the FMA dependency chain.
    const int warp = t >> 5, lane = t & 31;
#pragma unroll 1
    for (int pi = 0; pi < 8; pi++) {
        int pos = warp * 8 + pi;
        int ind = sInd[pos];
        const float4* W4 = g_moe4 + ind * 1024 + lane;   // [ind][cg][lane]
        const float4* X4 = (const float4*)(sAT + pos * TPAD);
        float h[4] = {0.0f, 0.0f, 0.0f, 0.0f};
#pragma unroll
        for (int blk = 0; blk < 4; blk++) {
            float4 w[8];
#pragma unroll
            for (int u = 0; u < 8; u++)
                w[u] = __ldg(W4 + (blk * 8 + u) * 32);
            float4 x[8];
#pragma unroll
            for (int u = 0; u < 8; u++)
                x[u] = X4[blk * 8 + u];
#pragma unroll
            for (int u = 0; u < 8; u++) {
                float s = h[u & 3];
                s = fmaf(x[u].x, w[u].x, s);
                s = fmaf(x[u].y, w[u].y, s);
                s = fmaf(x[u].z, w[u].z, s);
                s = fmaf(x[u].w, w[u].w, s);
                h[u & 3] = s;
            }
        }
        float hs = lrelu((h[0] + h[1]) + (h[2] + h[3]) + __ldg(cm2_b + ind * 32 + lane));
        float r = hs * __ldg(cm3_w + ind * 32 + lane);
#pragma unroll
        for (int off = 16; off; off >>= 1)
            r += __shfl_down_sync(0xffffffffu, r, off);
        if (lane == 0)
            out[bb * 8192 + w0 + pos] =
                ((float)ind + r + __ldg(cm3_b + ind)) * (1.0f / 128.0f);
    }
}

// ---------------- launch ----------------
extern "C" void kernel_launch(void* const* d_in, const int* in_sizes, int n_in,
                              void* d_out, int out_size)
{
    const float* x_in  = (const float*)d_in[0];
    const float* cl1_w = (const float*)d_in[1];
    const float* cl1_b = (const float*)d_in[2];
    const float* bn1_g = (const float*)d_in[3];
    const float* bn1_b = (const float*)d_in[4];
    const float* bn1_m = (const float*)d_in[5];
    const float* bn1_v = (const float*)d_in[6];
    const float* cl2_w = (const float*)d_in[7];
    const float* cl2_b = (const float*)d_in[8];
    const float* cl3_w = (const float*)d_in[9];
    const float* cl3_b = (const float*)d_in[10];
    const float* reg1_w = (const float*)d_in[11];
    const float* reg1_b = (const float*)d_in[12];
    const float* bnr_g = (const float*)d_in[13];
    const float* bnr_b = (const float*)d_in[14];
    const float* bnr_m = (const float*)d_in[15];
    const float* bnr_v = (const float*)d_in[16];
    const float* cm2_w = (const float*)d_in[17];
    const float* cm2_b = (const float*)d_in[18];
    const float* cm3_w = (const float*)d_in[19];
    const float* cm3_b = (const float*)d_in[20];
    float* out = (float*)d_out;

    // region0(64*TPAD) + sB(128*PAD) + sW(2048) + sInd(64)
    const int SMEM_BYTES = (64 * TPAD + 128 * PAD + 2048 + 64) * 4;  // 75008 B

    cudaFuncSetAttribute(fused_kernel, cudaFuncAttributeMaxDynamicSharedMemorySize,
                         SMEM_BYTES);

    prep_all_kernel<<<512, 256>>>(cl1_w, cl1_b, bn1_g, bn1_b, bn1_m, bn1_v,
                                  cl2_w, cl2_b, cl3_w, cl3_b,
                                  reg1_w, reg1_b, bnr_g, bnr_b, bnr_m, bnr_v,
                                  cm2_w);

    fused_kernel<<<1024, 256, SMEM_BYTES>>>(x_in, cm2_b, cm3_w, cm3_b, out);
}

// round 7
// speedup vs baseline: 1.0923x; 1.0923x over previous
#include <cuda_runtime.h>

#define SLOPE 0.01f
#define EPSBN 1e-5f
#define TILE  64
#define PAD   64
#define TPAD  132     // row stride (floats) of transposed xr tile; %4==0 for LDS.128
#define NPOS  65536

// ---------------- device scratch (no allocations allowed) ----------------
__device__ float g_w1t[16384];   // [k][o] transposed, BN-folded
__device__ float g_w2t[16384];
__device__ float g_w3t[16384];   // logits rows only (o<128)
__device__ float g_wrt[16384];   // reg1, BN-folded
__device__ float g_b1[128];
__device__ float g_b2[128];
__device__ float g_b3[128];
__device__ float g_br[128];
__device__ float g_wm[128];      // mask row of cl3_w (o==128)
__device__ float g_bm;
__device__ float4 g_moe4[131072]; // [expert][c/4][lane] float4 repack of cm2_w (2MB)

__device__ __forceinline__ float lrelu(float v) { return v >= 0.0f ? v : SLOPE * v; }

// packed f32x2 helpers (FFMA2 path — ptxas never emits this, PTX only)
__device__ __forceinline__ unsigned long long pk2(float x) {
    unsigned long long r;
    asm("mov.b64 %0, {%1, %1};" : "=l"(r) : "f"(x));
    return r;
}
__device__ __forceinline__ void fma2(unsigned long long& d,
                                     unsigned long long a, unsigned long long b) {
    asm("fma.rn.f32x2 %0, %1, %2, %0;" : "+l"(d) : "l"(a), "l"(b));
}
__device__ __forceinline__ float2 up2(unsigned long long v) {
    float2 r;
    asm("mov.b64 {%0, %1}, %2;" : "=f"(r.x), "=f"(r.y) : "l"(v));
    return r;
}

// ---------------- merged prep: fold BN, transpose weights, repack MoE ----------------
__global__ void prep_all_kernel(const float* __restrict__ cl1_w, const float* __restrict__ cl1_b,
                                const float* __restrict__ g1,    const float* __restrict__ be1,
                                const float* __restrict__ m1,    const float* __restrict__ v1,
                                const float* __restrict__ cl2_w, const float* __restrict__ cl2_b,
                                const float* __restrict__ cl3_w, const float* __restrict__ cl3_b,
                                const float* __restrict__ reg1_w,const float* __restrict__ reg1_b,
                                const float* __restrict__ gr,    const float* __restrict__ ber,
                                const float* __restrict__ mr,    const float* __restrict__ vr,
                                const float* __restrict__ cm2_w)
{
    int tid = blockIdx.x * blockDim.x + threadIdx.x;   // 0..131071

    // MoE repack: [e][cg][lane] <- cm2_w[e][cg*4 + 0..3][lane]
    {
        int e  = tid >> 10;
        int cg = (tid >> 5) & 31;
        int j  = tid & 31;
        const float* src = cm2_w + e * 4096 + (cg * 4) * 32 + j;
        g_moe4[tid] = make_float4(src[0], src[32], src[64], src[96]);
    }

    if (tid < 16384) {
        int o = tid >> 7, k = tid & 127;
        float s1 = g1[o] * rsqrtf(v1[o] + EPSBN);
        float sr = gr[o] * rsqrtf(vr[o] + EPSBN);
        g_w1t[k * 128 + o] = cl1_w[o * 128 + k] * s1;
        g_wrt[k * 128 + o] = reg1_w[o * 128 + k] * sr;
        g_w2t[k * 128 + o] = cl2_w[o * 128 + k];
        g_w3t[k * 128 + o] = cl3_w[o * 128 + k];
    }
    if (tid < 128) {
        float s = g1[tid] * rsqrtf(v1[tid] + EPSBN);
        g_b1[tid] = cl1_b[tid] * s + be1[tid] - m1[tid] * s;
        float s2 = gr[tid] * rsqrtf(vr[tid] + EPSBN);
        g_br[tid] = reg1_b[tid] * s2 + ber[tid] - mr[tid] * s2;
        g_b2[tid] = cl2_b[tid];
        g_b3[tid] = cl3_b[tid];
        g_wm[tid] = cl3_w[128 * 128 + tid];
        if (tid == 0) g_bm = cl3_b[128];
    }
}

// ---------------- 128x128 x 64 GEMM tile via FFMA2, 8ch x 8pos per thread ----
// 128 threads: ty = t>>3 (16 ch-groups of 8), tx = t&7.
// Thread owns positions {tx*4..tx*4+3} and {32+tx*4..+3} (conflict-free LDS.128).
// f[8][8]: f[i][j] = channel ty*8+i, position (j<4 ? tx*4+j : 32+tx*4+j-4).
__device__ __forceinline__ void gemm_tile(const float* __restrict__ wT,
                                          const float* sIn, float* sW,
                                          float f[8][8])
{
    const int t  = threadIdx.x;
    const int ty = t >> 3, tx = t & 7;
    const float4* wg  = (const float4*)wT;
    float4*       ws4 = (float4*)sW;

    unsigned long long acc[4][8];
#pragma unroll
    for (int i = 0; i < 4; i++)
#pragma unroll
        for (int j = 0; j < 8; j++) acc[i][j] = 0ull;

    // prefetch chunk 0 (16 k-rows x 128 o = 512 float4, 4 per thread)
    float4 p0 = wg[t];
    float4 p1 = wg[t + 128];
    float4 p2 = wg[t + 256];
    float4 p3 = wg[t + 384];

#pragma unroll 1
    for (int kk = 0; kk < 8; kk++) {
        ws4[t]       = p0;
        ws4[t + 128] = p1;
        ws4[t + 256] = p2;
        ws4[t + 384] = p3;
        __syncthreads();
        if (kk < 7) {
            p0 = wg[(kk + 1) * 512 + t];
            p1 = wg[(kk + 1) * 512 + 128 + t];
            p2 = wg[(kk + 1) * 512 + 256 + t];
            p3 = wg[(kk + 1) * 512 + 384 + t];
        }
        const float* inb = sIn + kk * 16 * PAD;
#pragma unroll
        for (int k = 0; k < 16; k++) {
            // channel pairs packed straight out of LDS.128 (broadcast per 8 lanes)
            ulonglong2 a01 = *(const ulonglong2*)(sW + k * 128 + ty * 8);
            ulonglong2 a23 = *(const ulonglong2*)(sW + k * 128 + ty * 8 + 4);
            float4 xlo = *(const float4*)(inb + k * PAD + tx * 4);
            float4 xhi = *(const float4*)(inb + k * PAD + 32 + tx * 4);
            unsigned long long b[8];
            b[0] = pk2(xlo.x); b[1] = pk2(xlo.y); b[2] = pk2(xlo.z); b[3] = pk2(xlo.w);
            b[4] = pk2(xhi.x); b[5] = pk2(xhi.y); b[6] = pk2(xhi.z); b[7] = pk2(xhi.w);
#pragma unroll
            for (int j = 0; j < 8; j++) {
                fma2(acc[0][j], a01.x, b[j]);
                fma2(acc[1][j], a01.y, b[j]);
                fma2(acc[2][j], a23.x, b[j]);
                fma2(acc[3][j], a23.y, b[j]);
            }
        }
        __syncthreads();
    }

#pragma unroll
    for (int ip = 0; ip < 4; ip++)
#pragma unroll
        for (int j = 0; j < 8; j++) {
            float2 u = up2(acc[ip][j]);
            f[2 * ip][j]     = u.x;
            f[2 * ip + 1][j] = u.y;
        }
}

// epilogue store helper: lrelu(f + bias) -> dst[ch][PAD] tile
__device__ __forceinline__ void store_act(float* dst, const float* bias,
                                          float f[8][8], int ty, int tx)
{
#pragma unroll
    for (int i = 0; i < 8; i++) {
        float bi = bias[ty * 8 + i];
#pragma unroll
        for (int j = 0; j < 8; j++) f[i][j] = lrelu(f[i][j] + bi);
        *(float4*)(dst + (ty * 8 + i) * PAD + tx * 4) =
            make_float4(f[i][0], f[i][1], f[i][2], f[i][3]);
        *(float4*)(dst + (ty * 8 + i) * PAD + 32 + tx * 4) =
            make_float4(f[i][4], f[i][5], f[i][6], f[i][7]);
    }
}

// ---------------- fused main kernel (128 threads) ----------------
__global__ void __launch_bounds__(128, 3)
fused_kernel(const float* __restrict__ x_in,
             const float* __restrict__ cm2_b,
             const float* __restrict__ cm3_w, const float* __restrict__ cm3_b,
             float* __restrict__ out)
{
    extern __shared__ float sm[];
    float* sA   = sm;                      // x tile as [128][PAD] (32768 < 64*TPAD)
    float* sAT  = sm;                      // xr tile as [64][TPAD] (same region)
    float* sB   = sm + 64 * TPAD;          // 128 * PAD
    float* sW   = sB + 128 * PAD;          // 16 * 128 staging
    float* sRv  = sW;                      // alias: argmax vals (sW dead by then)
    int*   sRi  = (int*)(sW + 1024);       // alias: argmax idx
    int*   sInd = (int*)(sW + 2048);       // 64

    const int t  = threadIdx.x;
    const int ty = t >> 3, tx = t & 7;
    const int bb = blockIdx.x >> 7;            // batch (8192/64 = 128 tiles per batch)
    const int w0 = (blockIdx.x & 127) * TILE;  // position offset within batch
    const float* xb = x_in + (size_t)bb * 128 * 8192 + w0;

    // stage x_in tile: [c][pos], 16 float4 per thread
#pragma unroll
    for (int j = 0; j < 16; j++) {
        int idx = t + j * 128;
        int c = idx >> 4, p4 = idx & 15;
        float4 v = *(const float4*)(xb + c * 8192 + p4 * 4);
        *(float4*)(sA + c * PAD + p4 * 4) = v;
    }
    __syncthreads();

    float f[8][8];

    // ---- L1: y1 = lrelu(bn(cl1 @ x)) : sA -> sB ----
    gemm_tile(g_w1t, sA, sW, f);
    store_act(sB, g_b1, f, ty, tx);

    // ---- R1: xr = lrelu(bn(reg1 @ x)) : sA -> TRANSPOSED sAT[pos][ch] ----
    gemm_tile(g_wrt, sA, sW, f);   // final sync inside: all reads of sA done
#pragma unroll
    for (int i = 0; i < 8; i++) {
        float bi = g_br[ty * 8 + i];
#pragma unroll
        for (int j = 0; j < 8; j++) f[i][j] = lrelu(f[i][j] + bi);
    }
#pragma unroll
    for (int j = 0; j < 8; j++) {
        int pos = (j < 4) ? (tx * 4 + j) : (32 + tx * 4 + j - 4);
#pragma unroll
        for (int ip = 0; ip < 4; ip++)
            *(float2*)(sAT + pos * TPAD + ty * 8 + 2 * ip) =
                make_float2(f[2 * ip][j], f[2 * ip + 1][j]);
    }

    // ---- L2: y2 = lrelu(cl2 @ y1) : sB -> sB ----
    gemm_tile(g_w2t, sB, sW, f);   // first sync inside orders the sAT/sB writes above
    store_act(sB, g_b2, f, ty, tx);

    // ---- L3: logits = cl3 @ y2 (128 channels) : sB -> regs ----
    gemm_tile(g_w3t, sB, sW, f);   // after final sync, sW is dead -> alias OK

    // local argmax over this thread's 8 channels (first-occurrence on ties)
#pragma unroll
    for (int j = 0; j < 8; j++) {
        int pos = (j < 4) ? (tx * 4 + j) : (32 + tx * 4 + j - 4);
        float bv = f[0][j] + g_b3[ty * 8];
        int bi = 0;
#pragma unroll
        for (int i = 1; i < 8; i++) {
            float v = f[i][j] + g_b3[ty * 8 + i];
            if (v > bv) { bv = v; bi = i; }
        }
        sRv[ty * 64 + pos] = bv;
        sRi[ty * 64 + pos] = ty * 8 + bi;
    }
    __syncthreads();

    if (t < 64) {
        // reduce argmax across 16 channel groups (ascending -> first occurrence kept)
        float bv = sRv[t];
        int bi = sRi[t];
#pragma unroll
        for (int r = 1; r < 16; r++) {
            float v = sRv[r * 64 + t];
            if (v > bv) { bv = v; bi = sRi[r * 64 + t]; }
        }
        sInd[t] = bi;
    } else {
        // mask channel: dot(y2[:,p], wm) + bm via 4 partial chains, lrelu
        int p = t - 64;
        float m0 = g_bm, m1 = 0.0f, m2 = 0.0f, m3 = 0.0f;
#pragma unroll 8
        for (int k = 0; k < 128; k += 4) {
            m0 = fmaf(sB[(k + 0) * PAD + p], g_wm[k + 0], m0);
            m1 = fmaf(sB[(k + 1) * PAD + p], g_wm[k + 1], m1);
            m2 = fmaf(sB[(k + 2) * PAD + p], g_wm[k + 2], m2);
            m3 = fmaf(sB[(k + 3) * PAD + p], g_wm[k + 3], m3);
        }
        out[NPOS + bb * 8192 + w0 + p] = lrelu((m0 + m1) + (m2 + m3));
    }
    __syncthreads();

    // ---- MoE regression: warp per position (4 warps x 16 pos) ----
    const int warp = t >> 5, lane = t & 31;
#pragma unroll 1
    for (int pi = 0; pi < 16; pi++) {
        int pos = warp * 16 + pi;
        int ind = sInd[pos];
        const float4* W4 = g_moe4 + ind * 1024 + lane;   // [ind][cg][lane]
        const float4* X4 = (const float4*)(sAT + pos * TPAD);
        float h[4] = {0.0f, 0.0f, 0.0f, 0.0f};
#pragma unroll
        for (int blk = 0; blk < 4; blk++) {
            float4 w[8];
#pragma unroll
            for (int u = 0; u < 8; u++)
                w[u] = __ldg(W4 + (blk * 8 + u) * 32);
            float4 x[8];
#pragma unroll
            for (int u = 0; u < 8; u++)
                x[u] = X4[blk * 8 + u];
#pragma unroll
            for (int u = 0; u < 8; u++) {
                float s = h[u & 3];
                s = fmaf(x[u].x, w[u].x, s);
                s = fmaf(x[u].y, w[u].y, s);
                s = fmaf(x[u].z, w[u].z, s);
                s = fmaf(x[u].w, w[u].w, s);
                h[u & 3] = s;
            }
        }
        float hs = lrelu((h[0] + h[1]) + (h[2] + h[3]) + __ldg(cm2_b + ind * 32 + lane));
        float r = hs * __ldg(cm3_w + ind * 32 + lane);
#pragma unroll
        for (int off = 16; off; off >>= 1)
            r += __shfl_down_sync(0xffffffffu, r, off);
        if (lane == 0)
            out[bb * 8192 + w0 + pos] =
                ((float)ind + r + __ldg(cm3_b + ind)) * (1.0f / 128.0f);
    }
}

// ---------------- launch ----------------
extern "C" void kernel_launch(void* const* d_in, const int* in_sizes, int n_in,
                              void* d_out, int out_size)
{
    const float* x_in  = (const float*)d_in[0];
    const float* cl1_w = (const float*)d_in[1];
    const float* cl1_b = (const float*)d_in[2];
    const float* bn1_g = (const float*)d_in[3];
    const float* bn1_b = (const float*)d_in[4];
    const float* bn1_m = (const float*)d_in[5];
    const float* bn1_v = (const float*)d_in[6];
    const float* cl2_w = (const float*)d_in[7];
    const float* cl2_b = (const float*)d_in[8];
    const float* cl3_w = (const float*)d_in[9];
    const float* cl3_b = (const float*)d_in[10];
    const float* reg1_w = (const float*)d_in[11];
    const float* reg1_b = (const float*)d_in[12];
    const float* bnr_g = (const float*)d_in[13];
    const float* bnr_b = (const float*)d_in[14];
    const float* bnr_m = (const float*)d_in[15];
    const float* bnr_v = (const float*)d_in[16];
    const float* cm2_w = (const float*)d_in[17];
    const float* cm2_b = (const float*)d_in[18];
    const float* cm3_w = (const float*)d_in[19];
    const float* cm3_b = (const float*)d_in[20];
    float* out = (float*)d_out;

    // region0(64*TPAD) + sB(128*PAD) + sW(2048) + sInd(64)
    const int SMEM_BYTES = (64 * TPAD + 128 * PAD + 2048 + 64) * 4;  // 75008 B

    cudaFuncSetAttribute(fused_kernel, cudaFuncAttributeMaxDynamicSharedMemorySize,
                         SMEM_BYTES);

    prep_all_kernel<<<512, 256>>>(cl1_w, cl1_b, bn1_g, bn1_b, bn1_m, bn1_v,
                                  cl2_w, cl2_b, cl3_w, cl3_b,
                                  reg1_w, reg1_b, bnr_g, bnr_b, bnr_m, bnr_v,
                                  cm2_w);

    fused_kernel<<<1024, 128, SMEM_BYTES>>>(x_in, cm2_b, cm3_w, cm3_b, out);
}

// round 8
// speedup vs baseline: 1.0995x; 1.0066x over previous
#include <cuda_runtime.h>

#define SLOPE 0.01f
#define EPSBN 1e-5f
#define TILE  64
#define PAD   64
#define TPAD  132     // row stride (floats) of transposed xr tile; %4==0 for LDS.128
#define NPOS  65536

// ---------------- device scratch (no allocations allowed) ----------------
__device__ float g_w1t[16384];   // [k][o] transposed, BN-folded
__device__ float g_w2t[16384];
__device__ float g_w3t[16384];   // logits rows only (o<128)
__device__ float g_wrt[16384];   // reg1, BN-folded
__device__ float g_b1[128];
__device__ float g_b2[128];
__device__ float g_b3[128];
__device__ float g_br[128];
__device__ float g_wm[128];      // mask row of cl3_w (o==128)
__device__ float g_bm;
__device__ float4 g_moe4[131072]; // [expert][c/4][lane] float4 repack of cm2_w (2MB)

__device__ __forceinline__ float lrelu(float v) { return v >= 0.0f ? v : SLOPE * v; }

// packed f32x2 helpers (FFMA2 path — ptxas never emits this, PTX only)
__device__ __forceinline__ unsigned long long pk2(float x) {
    unsigned long long r;
    asm("mov.b64 %0, {%1, %1};" : "=l"(r) : "f"(x));
    return r;
}
__device__ __forceinline__ void fma2(unsigned long long& d,
                                     unsigned long long a, unsigned long long b) {
    asm("fma.rn.f32x2 %0, %1, %2, %0;" : "+l"(d) : "l"(a), "l"(b));
}
__device__ __forceinline__ float2 up2(unsigned long long v) {
    float2 r;
    asm("mov.b64 {%0, %1}, %2;" : "=f"(r.x), "=f"(r.y) : "l"(v));
    return r;
}

// ---------------- merged prep: fold BN, transpose weights, repack MoE ----------------
__global__ void prep_all_kernel(const float* __restrict__ cl1_w, const float* __restrict__ cl1_b,
                                const float* __restrict__ g1,    const float* __restrict__ be1,
                                const float* __restrict__ m1,    const float* __restrict__ v1,
                                const float* __restrict__ cl2_w, const float* __restrict__ cl2_b,
                                const float* __restrict__ cl3_w, const float* __restrict__ cl3_b,
                                const float* __restrict__ reg1_w,const float* __restrict__ reg1_b,
                                const float* __restrict__ gr,    const float* __restrict__ ber,
                                const float* __restrict__ mr,    const float* __restrict__ vr,
                                const float* __restrict__ cm2_w)
{
    int tid = blockIdx.x * blockDim.x + threadIdx.x;   // 0..131071

    // MoE repack: [e][cg][lane] <- cm2_w[e][cg*4 + 0..3][lane]
    {
        int e  = tid >> 10;
        int cg = (tid >> 5) & 31;
        int j  = tid & 31;
        const float* src = cm2_w + e * 4096 + (cg * 4) * 32 + j;
        g_moe4[tid] = make_float4(src[0], src[32], src[64], src[96]);
    }

    if (tid < 16384) {
        int o = tid >> 7, k = tid & 127;
        float s1 = g1[o] * rsqrtf(v1[o] + EPSBN);
        float sr = gr[o] * rsqrtf(vr[o] + EPSBN);
        g_w1t[k * 128 + o] = cl1_w[o * 128 + k] * s1;
        g_wrt[k * 128 + o] = reg1_w[o * 128 + k] * sr;
        g_w2t[k * 128 + o] = cl2_w[o * 128 + k];
        g_w3t[k * 128 + o] = cl3_w[o * 128 + k];
    }
    if (tid < 128) {
        float s = g1[tid] * rsqrtf(v1[tid] + EPSBN);
        g_b1[tid] = cl1_b[tid] * s + be1[tid] - m1[tid] * s;
        float s2 = gr[tid] * rsqrtf(vr[tid] + EPSBN);
        g_br[tid] = reg1_b[tid] * s2 + ber[tid] - mr[tid] * s2;
        g_b2[tid] = cl2_b[tid];
        g_b3[tid] = cl3_b[tid];
        g_wm[tid] = cl3_w[128 * 128 + tid];
        if (tid == 0) g_bm = cl3_b[128];
    }
}

// ---------------- 128x128 x 64 GEMM tile via FFMA2, 8ch x 8pos per thread ----
// 128 threads: ty = t>>3 (16 ch-groups of 8), tx = t&7.
// Thread owns positions {tx*4..tx*4+3} and {32+tx*4..+3} (conflict-free LDS.128).
// f[8][8]: f[i][j] = channel ty*8+i, position (j<4 ? tx*4+j : 32+tx*4+j-4).
__device__ __forceinline__ void gemm_tile(const float* __restrict__ wT,
                                          const float* sIn, float* sW,
                                          float f[8][8])
{
    const int t  = threadIdx.x;
    const int ty = t >> 3, tx = t & 7;
    const float4* wg  = (const float4*)wT;
    float4*       ws4 = (float4*)sW;

    unsigned long long acc[4][8];
#pragma unroll
    for (int i = 0; i < 4; i++)
#pragma unroll
        for (int j = 0; j < 8; j++) acc[i][j] = 0ull;

    // prefetch chunk 0 (16 k-rows x 128 o = 512 float4, 4 per thread)
    float4 p0 = wg[t];
    float4 p1 = wg[t + 128];
    float4 p2 = wg[t + 256];
    float4 p3 = wg[t + 384];

#pragma unroll 1
    for (int kk = 0; kk < 8; kk++) {
        ws4[t]       = p0;
        ws4[t + 128] = p1;
        ws4[t + 256] = p2;
        ws4[t + 384] = p3;
        __syncthreads();
        if (kk < 7) {
            p0 = wg[(kk + 1) * 512 + t];
            p1 = wg[(kk + 1) * 512 + 128 + t];
            p2 = wg[(kk + 1) * 512 + 256 + t];
            p3 = wg[(kk + 1) * 512 + 384 + t];
        }
        const float* inb = sIn + kk * 16 * PAD;
#pragma unroll
        for (int k = 0; k < 16; k++) {
            // channel pairs packed straight out of LDS.128 (broadcast per 8 lanes)
            ulonglong2 a01 = *(const ulonglong2*)(sW + k * 128 + ty * 8);
            ulonglong2 a23 = *(const ulonglong2*)(sW + k * 128 + ty * 8 + 4);
            float4 xlo = *(const float4*)(inb + k * PAD + tx * 4);
            float4 xhi = *(const float4*)(inb + k * PAD + 32 + tx * 4);
            unsigned long long b[8];
            b[0] = pk2(xlo.x); b[1] = pk2(xlo.y); b[2] = pk2(xlo.z); b[3] = pk2(xlo.w);
            b[4] = pk2(xhi.x); b[5] = pk2(xhi.y); b[6] = pk2(xhi.z); b[7] = pk2(xhi.w);
#pragma unroll
            for (int j = 0; j < 8; j++) {
                fma2(acc[0][j], a01.x, b[j]);
                fma2(acc[1][j], a01.y, b[j]);
                fma2(acc[2][j], a23.x, b[j]);
                fma2(acc[3][j], a23.y, b[j]);
            }
        }
        __syncthreads();
    }

#pragma unroll
    for (int ip = 0; ip < 4; ip++)
#pragma unroll
        for (int j = 0; j < 8; j++) {
            float2 u = up2(acc[ip][j]);
            f[2 * ip][j]     = u.x;
            f[2 * ip + 1][j] = u.y;
        }
}

// epilogue store helper: lrelu(f + bias) -> dst[ch][PAD] tile
__device__ __forceinline__ void store_act(float* dst, const float* bias,
                                          float f[8][8], int ty, int tx)
{
#pragma unroll
    for (int i = 0; i < 8; i++) {
        float bi = bias[ty * 8 + i];
#pragma unroll
        for (int j = 0; j < 8; j++) f[i][j] = lrelu(f[i][j] + bi);
        *(float4*)(dst + (ty * 8 + i) * PAD + tx * 4) =
            make_float4(f[i][0], f[i][1], f[i][2], f[i][3]);
        *(float4*)(dst + (ty * 8 + i) * PAD + 32 + tx * 4) =
            make_float4(f[i][4], f[i][5], f[i][6], f[i][7]);
    }
}

// ---------------- fused main kernel (128 threads) ----------------
__global__ void __launch_bounds__(128, 3)
fused_kernel(const float* __restrict__ x_in,
             const float* __restrict__ cm2_b,
             const float* __restrict__ cm3_w, const float* __restrict__ cm3_b,
             float* __restrict__ out)
{
    extern __shared__ float sm[];
    float* sA   = sm;                      // x tile as [128][PAD] (32768 < 64*TPAD)
    float* sAT  = sm;                      // xr tile as [64][TPAD] (same region)
    float* sB   = sm + 64 * TPAD;          // 128 * PAD
    float* sW   = sB + 128 * PAD;          // 16 * 128 staging
    float* sRv  = sW;                      // alias: argmax vals (sW dead by then)
    int*   sRi  = (int*)(sW + 1024);       // alias: argmax idx
    int*   sInd = (int*)(sW + 2048);       // 64

    const int t  = threadIdx.x;
    const int ty = t >> 3, tx = t & 7;
    const int bb = blockIdx.x >> 7;            // batch (8192/64 = 128 tiles per batch)
    const int w0 = (blockIdx.x & 127) * TILE;  // position offset within batch
    const float* xb = x_in + (size_t)bb * 128 * 8192 + w0;

    // stage x_in tile: [c][pos], 16 float4 per thread
#pragma unroll
    for (int j = 0; j < 16; j++) {
        int idx = t + j * 128;
        int c = idx >> 4, p4 = idx & 15;
        float4 v = *(const float4*)(xb + c * 8192 + p4 * 4);
        *(float4*)(sA + c * PAD + p4 * 4) = v;
    }
    __syncthreads();

    float f[8][8];

    // ---- L1: y1 = lrelu(bn(cl1 @ x)) : sA -> sB ----
    gemm_tile(g_w1t, sA, sW, f);
    store_act(sB, g_b1, f, ty, tx);

    // ---- R1: xr = lrelu(bn(reg1 @ x)) : sA -> TRANSPOSED sAT[pos][ch] ----
    gemm_tile(g_wrt, sA, sW, f);   // final sync inside: all reads of sA done
#pragma unroll
    for (int i = 0; i < 8; i++) {
        float bi = g_br[ty * 8 + i];
#pragma unroll
        for (int j = 0; j < 8; j++) f[i][j] = lrelu(f[i][j] + bi);
    }
#pragma unroll
    for (int j = 0; j < 8; j++) {
        int pos = (j < 4) ? (tx * 4 + j) : (32 + tx * 4 + j - 4);
#pragma unroll
        for (int ip = 0; ip < 4; ip++)
            *(float2*)(sAT + pos * TPAD + ty * 8 + 2 * ip) =
                make_float2(f[2 * ip][j], f[2 * ip + 1][j]);
    }

    // ---- L2: y2 = lrelu(cl2 @ y1) : sB -> sB ----
    gemm_tile(g_w2t, sB, sW, f);   // first sync inside orders the sAT/sB writes above
    store_act(sB, g_b2, f, ty, tx);

    // ---- L3: logits = cl3 @ y2 (128 channels) : sB -> regs ----
    gemm_tile(g_w3t, sB, sW, f);   // after final sync, sW is dead -> alias OK

    // local argmax over this thread's 8 channels (first-occurrence on ties)
#pragma unroll
    for (int j = 0; j < 8; j++) {
        int pos = (j < 4) ? (tx * 4 + j) : (32 + tx * 4 + j - 4);
        float bv = f[0][j] + g_b3[ty * 8];
        int bi = 0;
#pragma unroll
        for (int i = 1; i < 8; i++) {
            float v = f[i][j] + g_b3[ty * 8 + i];
            if (v > bv) { bv = v; bi = i; }
        }
        sRv[ty * 64 + pos] = bv;
        sRi[ty * 64 + pos] = ty * 8 + bi;
    }
    __syncthreads();

    if (t < 64) {
        // reduce argmax across 16 channel groups (ascending -> first occurrence kept)
        float bv = sRv[t];
        int bi = sRi[t];
#pragma unroll
        for (int r = 1; r < 16; r++) {
            float v = sRv[r * 64 + t];
            if (v > bv) { bv = v; bi = sRi[r * 64 + t]; }
        }
        sInd[t] = bi;
    } else {
        // mask channel: dot(y2[:,p], wm) + bm via 4 partial chains, lrelu
        int p = t - 64;
        float m0 = g_bm, m1 = 0.0f, m2 = 0.0f, m3 = 0.0f;
#pragma unroll 8
        for (int k = 0; k < 128; k += 4) {
            m0 = fmaf(sB[(k + 0) * PAD + p], g_wm[k + 0], m0);
            m1 = fmaf(sB[(k + 1) * PAD + p], g_wm[k + 1], m1);
            m2 = fmaf(sB[(k + 2) * PAD + p], g_wm[k + 2], m2);
            m3 = fmaf(sB[(k + 3) * PAD + p], g_wm[k + 3], m3);
        }
        out[NPOS + bb * 8192 + w0 + p] = lrelu((m0 + m1) + (m2 + m3));
    }
    __syncthreads();

    // ---- MoE regression: warp per position (4 warps x 16 pos) ----
    const int warp = t >> 5, lane = t & 31;
#pragma unroll 1
    for (int pi = 0; pi < 16; pi++) {
        int pos = warp * 16 + pi;
        int ind = sInd[pos];
        const float4* W4 = g_moe4 + ind * 1024 + lane;   // [ind][cg][lane]
        const float4* X4 = (const float4*)(sAT + pos * TPAD);
        float h[4] = {0.0f, 0.0f, 0.0f, 0.0f};
#pragma unroll
        for (int blk = 0; blk < 4; blk++) {
            float4 w[8];
#pragma unroll
            for (int u = 0; u < 8; u++)
                w[u] = __ldg(W4 + (blk * 8 + u) * 32);
            float4 x[8];
#pragma unroll
            for (int u = 0; u < 8; u++)
                x[u] = X4[blk * 8 + u];
#pragma unroll
            for (int u = 0; u < 8; u++) {
                float s = h[u & 3];
                s = fmaf(x[u].x, w[u].x, s);
                s = fmaf(x[u].y, w[u].y, s);
                s = fmaf(x[u].z, w[u].z, s);
                s = fmaf(x[u].w, w[u].w, s);
                h[u & 3] = s;
            }
        }
        float hs = lrelu((h[0] + h[1]) + (h[2] + h[3]) + __ldg(cm2_b + ind * 32 + lane));
        float r = hs * __ldg(cm3_w + ind * 32 + lane);
#pragma unroll
        for (int off = 16; off; off >>= 1)
            r += __shfl_down_sync(0xffffffffu, r, off);
        if (lane == 0)
            out[bb * 8192 + w0 + pos] =
                ((float)ind + r + __ldg(cm3_b + ind)) * (1.0f / 128.0f);
    }
}

// ---------------- launch ----------------
extern "C" void kernel_launch(void* const* d_in, const int* in_sizes, int n_in,
                              void* d_out, int out_size)
{
    const float* x_in  = (const float*)d_in[0];
    const float* cl1_w = (const float*)d_in[1];
    const float* cl1_b = (const float*)d_in[2];
    const float* bn1_g = (const float*)d_in[3];
    const float* bn1_b = (const float*)d_in[4];
    const float* bn1_m = (const float*)d_in[5];
    const float* bn1_v = (const float*)d_in[6];
    const float* cl2_w = (const float*)d_in[7];
    const float* cl2_b = (const float*)d_in[8];
    const float* cl3_w = (const float*)d_in[9];
    const float* cl3_b = (const float*)d_in[10];
    const float* reg1_w = (const float*)d_in[11];
    const float* reg1_b = (const float*)d_in[12];
    const float* bnr_g = (const float*)d_in[13];
    const float* bnr_b = (const float*)d_in[14];
    const float* bnr_m = (const float*)d_in[15];
    const float* bnr_v = (const float*)d_in[16];
    const float* cm2_w = (const float*)d_in[17];
    const float* cm2_b = (const float*)d_in[18];
    const float* cm3_w = (const float*)d_in[19];
    const float* cm3_b = (const float*)d_in[20];
    float* out = (float*)d_out;

    // region0(64*TPAD) + sB(128*PAD) + sW(2048) + sInd(64)
    const int SMEM_BYTES = (64 * TPAD + 128 * PAD + 2048 + 64) * 4;  // 75008 B

    cudaFuncSetAttribute(fused_kernel, cudaFuncAttributeMaxDynamicSharedMemorySize,
                         SMEM_BYTES);

    prep_all_kernel<<<512, 256>>>(cl1_w, cl1_b, bn1_g, bn1_b, bn1_m, bn1_v,
                                  cl2_w, cl2_b, cl3_w, cl3_b,
                                  reg1_w, reg1_b, bnr_g, bnr_b, bnr_m, bnr_v,
                                  cm2_w);

    fused_kernel<<<1024, 128, SMEM_BYTES>>>(x_in, cm2_b, cm3_w, cm3_b, out);
}

// round 9
// speedup vs baseline: 1.1126x; 1.0119x over previous
#include <cuda_runtime.h>

#define SLOPE 0.01f
#define EPSBN 1e-5f
#define TILE  64
#define PAD   64
#define TPAD  132     // row stride (floats) of transposed xr tile; %4==0 for LDS.128
#define NPOS  65536

// ---------------- device scratch (no allocations allowed) ----------------
__device__ float g_w1t[16384];   // [k][o] transposed, BN-folded
__device__ float g_w2t[16384];
__device__ float g_w3t[16384];   // logits rows only (o<128)
__device__ float g_wrt[16384];   // reg1, BN-folded
__device__ float g_b1[128];
__device__ float g_b2[128];
__device__ float g_b3[128];
__device__ float g_br[128];
__device__ float g_wm[128];      // mask row of cl3_w (o==128)
__device__ float g_bm;
__device__ float4 g_moe4[131072]; // [expert][c/4][lane] float4 repack of cm2_w (2MB)

__device__ __forceinline__ float lrelu(float v) { return v >= 0.0f ? v : SLOPE * v; }

// packed f32x2 helpers (FFMA2 path — ptxas never emits this, PTX only)
__device__ __forceinline__ unsigned long long pk2(float x) {
    unsigned long long r;
    asm("mov.b64 %0, {%1, %1};" : "=l"(r) : "f"(x));
    return r;
}
__device__ __forceinline__ void fma2(unsigned long long& d,
                                     unsigned long long a, unsigned long long b) {
    asm("fma.rn.f32x2 %0, %1, %2, %0;" : "+l"(d) : "l"(a), "l"(b));
}
__device__ __forceinline__ float2 up2(unsigned long long v) {
    float2 r;
    asm("mov.b64 {%0, %1}, %2;" : "=f"(r.x), "=f"(r.y) : "l"(v));
    return r;
}

// ---------------- merged prep: fold BN, transpose weights, repack MoE ----------------
__global__ void prep_all_kernel(const float* __restrict__ cl1_w, const float* __restrict__ cl1_b,
                                const float* __restrict__ g1,    const float* __restrict__ be1,
                                const float* __restrict__ m1,    const float* __restrict__ v1,
                                const float* __restrict__ cl2_w, const float* __restrict__ cl2_b,
                                const float* __restrict__ cl3_w, const float* __restrict__ cl3_b,
                                const float* __restrict__ reg1_w,const float* __restrict__ reg1_b,
                                const float* __restrict__ gr,    const float* __restrict__ ber,
                                const float* __restrict__ mr,    const float* __restrict__ vr,
                                const float* __restrict__ cm2_w)
{
    int tid = blockIdx.x * blockDim.x + threadIdx.x;   // 0..131071

    // MoE repack: [e][cg][lane] <- cm2_w[e][cg*4 + 0..3][lane]
    {
        int e  = tid >> 10;
        int cg = (tid >> 5) & 31;
        int j  = tid & 31;
        const float* src = cm2_w + e * 4096 + (cg * 4) * 32 + j;
        g_moe4[tid] = make_float4(src[0], src[32], src[64], src[96]);
    }

    if (tid < 16384) {
        int o = tid >> 7, k = tid & 127;
        float s1 = g1[o] * rsqrtf(v1[o] + EPSBN);
        float sr = gr[o] * rsqrtf(vr[o] + EPSBN);
        g_w1t[k * 128 + o] = cl1_w[o * 128 + k] * s1;
        g_wrt[k * 128 + o] = reg1_w[o * 128 + k] * sr;
        g_w2t[k * 128 + o] = cl2_w[o * 128 + k];
        g_w3t[k * 128 + o] = cl3_w[o * 128 + k];
    }
    if (tid < 128) {
        float s = g1[tid] * rsqrtf(v1[tid] + EPSBN);
        g_b1[tid] = cl1_b[tid] * s + be1[tid] - m1[tid] * s;
        float s2 = gr[tid] * rsqrtf(vr[tid] + EPSBN);
        g_br[tid] = reg1_b[tid] * s2 + ber[tid] - mr[tid] * s2;
        g_b2[tid] = cl2_b[tid];
        g_b3[tid] = cl3_b[tid];
        g_wm[tid] = cl3_w[128 * 128 + tid];
        if (tid == 0) g_bm = cl3_b[128];
    }
}

// ---------------- 128x128 x 64 GEMM tile via FFMA2, warp-private staging ----
// 128 threads: ty = t>>3 (16 ch-groups of 8), tx = t&7.
// Warp w owns output channels 32w..32w+31 and stages ONLY its own weight
// slice [16 k][32 ch] (2KB) into its private sW region -> only __syncwarp
// needed inside the GEMM, no __syncthreads. Caller handles inter-layer
// hazards on sIn/output buffers.
// f[8][8]: f[i][j] = channel ty*8+i, position (j<4 ? tx*4+j : 32+tx*4+j-4).
__device__ __forceinline__ void gemm_tile(const float* __restrict__ wT,
                                          const float* sIn, float* sWb,
                                          float f[8][8])
{
    const int t    = threadIdx.x;
    const int warp = t >> 5, lane = t & 31;
    const int ty   = t >> 3, tx = t & 7;
    const int tyl  = ty & 3;               // channel group within warp
    const int lk   = lane >> 3, lc = lane & 7;
    const float4* wg  = (const float4*)wT;
    float*  sW  = sWb + warp * 512;         // [16 k][32 ch] floats
    float4* ws4 = (float4*)sW;

    unsigned long long acc[4][8];
#pragma unroll
    for (int i = 0; i < 4; i++)
#pragma unroll
        for (int j = 0; j < 8; j++) acc[i][j] = 0ull;

    // prefetch chunk 0: warp loads its [16k][32ch] slice, 4 float4/lane
    // global float4 index for (k, c4) = k*32 + warp*8 + c4
    float4 p[4];
#pragma unroll
    for (int j = 0; j < 4; j++)
        p[j] = wg[(lk + 4 * j) * 32 + warp * 8 + lc];

#pragma unroll 1
    for (int kk = 0; kk < 8; kk++) {
#pragma unroll
        for (int j = 0; j < 4; j++)
            ws4[(lk + 4 * j) * 8 + lc] = p[j];
        __syncwarp();
        if (kk < 7) {
#pragma unroll
            for (int j = 0; j < 4; j++)
                p[j] = wg[((kk + 1) * 16 + lk + 4 * j) * 32 + warp * 8 + lc];
        }
        const float* inb = sIn + kk * 16 * PAD;
#pragma unroll
        for (int k = 0; k < 16; k++) {
            // channel pairs packed straight out of LDS.128 (broadcast per 8 lanes)
            ulonglong2 a01 = *(const ulonglong2*)(sW + k * 32 + tyl * 8);
            ulonglong2 a23 = *(const ulonglong2*)(sW + k * 32 + tyl * 8 + 4);
            float4 xlo = *(const float4*)(inb + k * PAD + tx * 4);
            float4 xhi = *(const float4*)(inb + k * PAD + 32 + tx * 4);
            unsigned long long b[8];
            b[0] = pk2(xlo.x); b[1] = pk2(xlo.y); b[2] = pk2(xlo.z); b[3] = pk2(xlo.w);
            b[4] = pk2(xhi.x); b[5] = pk2(xhi.y); b[6] = pk2(xhi.z); b[7] = pk2(xhi.w);
#pragma unroll
            for (int j = 0; j < 8; j++) {
                fma2(acc[0][j], a01.x, b[j]);
                fma2(acc[1][j], a01.y, b[j]);
                fma2(acc[2][j], a23.x, b[j]);
                fma2(acc[3][j], a23.y, b[j]);
            }
        }
        __syncwarp();
    }

#pragma unroll
    for (int ip = 0; ip < 4; ip++)
#pragma unroll
        for (int j = 0; j < 8; j++) {
            float2 u = up2(acc[ip][j]);
            f[2 * ip][j]     = u.x;
            f[2 * ip + 1][j] = u.y;
        }
}

// epilogue store helper: lrelu(f + bias) -> dst[ch][PAD] tile
__device__ __forceinline__ void store_act(float* dst, const float* bias,
                                          float f[8][8], int ty, int tx)
{
#pragma unroll
    for (int i = 0; i < 8; i++) {
        float bi = bias[ty * 8 + i];
#pragma unroll
        for (int j = 0; j < 8; j++) f[i][j] = lrelu(f[i][j] + bi);
        *(float4*)(dst + (ty * 8 + i) * PAD + tx * 4) =
            make_float4(f[i][0], f[i][1], f[i][2], f[i][3]);
        *(float4*)(dst + (ty * 8 + i) * PAD + 32 + tx * 4) =
            make_float4(f[i][4], f[i][5], f[i][6], f[i][7]);
    }
}

// ---------------- fused main kernel (128 threads) ----------------
__global__ void __launch_bounds__(128, 3)
fused_kernel(const float* __restrict__ x_in,
             const float* __restrict__ cm2_b,
             const float* __restrict__ cm3_w, const float* __restrict__ cm3_b,
             float* __restrict__ out)
{
    extern __shared__ float sm[];
    float* sA   = sm;                      // x tile as [128][PAD] (32768 < 64*TPAD)
    float* sAT  = sm;                      // xr tile as [64][TPAD] (same region)
    float* sB   = sm + 64 * TPAD;          // 128 * PAD
    float* sW   = sB + 128 * PAD;          // 4 x 512 warp-private staging
    float* sRv  = sW;                      // alias: argmax vals (sW dead by then)
    int*   sRi  = (int*)(sW + 1024);       // alias: argmax idx
    int*   sInd = (int*)(sW + 2048);       // 64

    const int t  = threadIdx.x;
    const int ty = t >> 3, tx = t & 7;
    const int bb = blockIdx.x >> 7;            // batch (8192/64 = 128 tiles per batch)
    const int w0 = (blockIdx.x & 127) * TILE;  // position offset within batch
    const float* xb = x_in + (size_t)bb * 128 * 8192 + w0;

    // stage x_in tile: [c][pos], 16 float4 per thread
#pragma unroll
    for (int j = 0; j < 16; j++) {
        int idx = t + j * 128;
        int c = idx >> 4, p4 = idx & 15;
        float4 v = *(const float4*)(xb + c * 8192 + p4 * 4);
        *(float4*)(sA + c * PAD + p4 * 4) = v;
    }
    __syncthreads();   // (1) x tile visible to all warps

    float f[8][8];

    // ---- L1: y1 = lrelu(bn(cl1 @ x)) : sA -> sB (no hazard, warps drift) ----
    gemm_tile(g_w1t, sA, sW, f);
    store_act(sB, g_b1, f, ty, tx);

    // ---- R1: xr = lrelu(bn(reg1 @ x)) : sA -> TRANSPOSED sAT[pos][ch] ----
    gemm_tile(g_wrt, sA, sW, f);
    __syncthreads();   // (2) all warps done reading sA before sAT overwrites it
#pragma unroll
    for (int i = 0; i < 8; i++) {
        float bi = g_br[ty * 8 + i];
#pragma unroll
        for (int j = 0; j < 8; j++) f[i][j] = lrelu(f[i][j] + bi);
    }
#pragma unroll
    for (int j = 0; j < 8; j++) {
        int pos = (j < 4) ? (tx * 4 + j) : (32 + tx * 4 + j - 4);
#pragma unroll
        for (int ip = 0; ip < 4; ip++)
            *(float2*)(sAT + pos * TPAD + ty * 8 + 2 * ip) =
                make_float2(f[2 * ip][j], f[2 * ip + 1][j]);
    }
    __syncthreads();   // (3) sAT + sB(y1) complete before L2 reads sB

    // ---- L2: y2 = lrelu(cl2 @ y1) : sB -> sB ----
    gemm_tile(g_w2t, sB, sW, f);
    __syncthreads();   // (4) all warps done reading y1 before overwrite
    store_act(sB, g_b2, f, ty, tx);
    __syncthreads();   // (5) y2 complete before L3 reads sB

    // ---- L3: logits = cl3 @ y2 (128 channels) : sB -> regs ----
    gemm_tile(g_w3t, sB, sW, f);
    __syncthreads();   // (6) all warps done with their sW slice before sRv alias

    // local argmax over this thread's 8 channels (first-occurrence on ties)
#pragma unroll
    for (int j = 0; j < 8; j++) {
        int pos = (j < 4) ? (tx * 4 + j) : (32 + tx * 4 + j - 4);
        float bv = f[0][j] + g_b3[ty * 8];
        int bi = 0;
#pragma unroll
        for (int i = 1; i < 8; i++) {
            float v = f[i][j] + g_b3[ty * 8 + i];
            if (v > bv) { bv = v; bi = i; }
        }
        sRv[ty * 64 + pos] = bv;
        sRi[ty * 64 + pos] = ty * 8 + bi;
    }
    __syncthreads();   // (7) argmax partials visible

    if (t < 64) {
        // reduce argmax across 16 channel groups (ascending -> first occurrence kept)
        float bv = sRv[t];
        int bi = sRi[t];
#pragma unroll
        for (int r = 1; r < 16; r++) {
            float v = sRv[r * 64 + t];
            if (v > bv) { bv = v; bi = sRi[r * 64 + t]; }
        }
        sInd[t] = bi;
    } else {
        // mask channel: dot(y2[:,p], wm) + bm via 4 partial chains, lrelu
        int p = t - 64;
        float m0 = g_bm, m1 = 0.0f, m2 = 0.0f, m3 = 0.0f;
#pragma unroll 8
        for (int k = 0; k < 128; k += 4) {
            m0 = fmaf(sB[(k + 0) * PAD + p], g_wm[k + 0], m0);
            m1 = fmaf(sB[(k + 1) * PAD + p], g_wm[k + 1], m1);
            m2 = fmaf(sB[(k + 2) * PAD + p], g_wm[k + 2], m2);
            m3 = fmaf(sB[(k + 3) * PAD + p], g_wm[k + 3], m3);
        }
        out[NPOS + bb * 8192 + w0 + p] = lrelu((m0 + m1) + (m2 + m3));
    }
    __syncthreads();   // (8) sInd visible

    // ---- MoE regression: warp per position (4 warps x 16 pos) ----
    const int warp = t >> 5, lane = t & 31;
#pragma unroll 1
    for (int pi = 0; pi < 16; pi++) {
        int pos = warp * 16 + pi;
        int ind = sInd[pos];
        const float4* W4 = g_moe4 + ind * 1024 + lane;   // [ind][cg][lane]
        const float4* X4 = (const float4*)(sAT + pos * TPAD);
        float h[4] = {0.0f, 0.0f, 0.0f, 0.0f};
#pragma unroll
        for (int blk = 0; blk < 4; blk++) {
            float4 w[8];
#pragma unroll
            for (int u = 0; u < 8; u++)
                w[u] = __ldg(W4 + (blk * 8 + u) * 32);
            float4 x[8];
#pragma unroll
            for (int u = 0; u < 8; u++)
                x[u] = X4[blk * 8 + u];
#pragma unroll
            for (int u = 0; u < 8; u++) {
                float s = h[u & 3];
                s = fmaf(x[u].x, w[u].x, s);
                s = fmaf(x[u].y, w[u].y, s);
                s = fmaf(x[u].z, w[u].z, s);
                s = fmaf(x[u].w, w[u].w, s);
                h[u & 3] = s;
            }
        }
        float hs = lrelu((h[0] + h[1]) + (h[2] + h[3]) + __ldg(cm2_b + ind * 32 + lane));
        float r = hs * __ldg(cm3_w + ind * 32 + lane);
#pragma unroll
        for (int off = 16; off; off >>= 1)
            r += __shfl_down_sync(0xffffffffu, r, off);
        if (lane == 0)
            out[bb * 8192 + w0 + pos] =
                ((float)ind + r + __ldg(cm3_b + ind)) * (1.0f / 128.0f);
    }
}

// ---------------- launch ----------------
extern "C" void kernel_launch(void* const* d_in, const int* in_sizes, int n_in,
                              void* d_out, int out_size)
{
    const float* x_in  = (const float*)d_in[0];
    const float* cl1_w = (const float*)d_in[1];
    const float* cl1_b = (const float*)d_in[2];
    const float* bn1_g = (const float*)d_in[3];
    const float* bn1_b = (const float*)d_in[4];
    const float* bn1_m = (const float*)d_in[5];
    const float* bn1_v = (const float*)d_in[6];
    const float* cl2_w = (const float*)d_in[7];
    const float* cl2_b = (const float*)d_in[8];
    const float* cl3_w = (const float*)d_in[9];
    const float* cl3_b = (const float*)d_in[10];
    const float* reg1_w = (const float*)d_in[11];
    const float* reg1_b = (const float*)d_in[12];
    const float* bnr_g = (const float*)d_in[13];
    const float* bnr_b = (const float*)d_in[14];
    const float* bnr_m = (const float*)d_in[15];
    const float* bnr_v = (const float*)d_in[16];
    const float* cm2_w = (const float*)d_in[17];
    const float* cm2_b = (const float*)d_in[18];
    const float* cm3_w = (const float*)d_in[19];
    const float* cm3_b = (const float*)d_in[20];
    float* out = (float*)d_out;

    // region0(64*TPAD) + sB(128*PAD) + sW(2048) + sInd(64)
    const int SMEM_BYTES = (64 * TPAD + 128 * PAD + 2048 + 64) * 4;  // 75008 B

    cudaFuncSetAttribute(fused_kernel, cudaFuncAttributeMaxDynamicSharedMemorySize,
                         SMEM_BYTES);

    prep_all_kernel<<<512, 256>>>(cl1_w, cl1_b, bn1_g, bn1_b, bn1_m, bn1_v,
                                  cl2_w, cl2_b, cl3_w, cl3_b,
                                  reg1_w, reg1_b, bnr_g, bnr_b, bnr_m, bnr_v,
                                  cm2_w);

    fused_kernel<<<1024, 128, SMEM_BYTES>>>(x_in, cm2_b, cm3_w, cm3_b, out);
}